// round 7
// baseline (speedup 1.0000x reference)
#include <cuda_runtime.h>
#include <cstdint>

typedef uint32_t u32;

#define N_TOK 1024
#define TZ 128
#define TD 64
#define NB 38
#define EPSF 1e-5f
#define TM 128
#define THREADS 256
#define NBLOCKS 152
#define NTILES ((N_TOK * N_TOK) / TM)   // 8192

// smem strides (floats) — chosen for conflict-free fragment loads
#define ZSTR 132     // 132 % 32 == 4 -> A-fragment bank == lane
#define VSTR 68      // 68 % 32 == 4
#define W1STR 72     // 72 % 32 == 8 -> B-fragment conflict-free
#define W2STR 136    // 136 % 32 == 8

// smem float offsets
#define ZA0_F 0                       // z buf0 128x132
#define ZA1_F (TM * ZSTR)             // z buf1
#define W1_F  (2 * TM * ZSTR)         // W1'[k][n] 128x72
#define W2_F  (W1_F + TZ * W1STR)     // W2 [d][c] 64x136
#define WAS_F (W2_F + TD * W2STR)     // Wa [bin][d] 38x64
#define S_F   (WAS_F + NB * TD)
#define T_F   (S_F + TD)
#define VG_F  (T_F + TD)
#define VB_F  (VG_F + TD)
#define LN2_F (VB_F + TD)             // float4[128] (s,q per col-half)
#define SMEM_FLOATS (LN2_F + 4 * TM)

// ---------------- helpers ----------------
__device__ __forceinline__ float rna_tf32(float x) {
    u32 r;
    asm("cvt.rna.tf32.f32 %0, %1;" : "=r"(r) : "f"(x));
    return __uint_as_float(r);
}
__device__ __forceinline__ u32 rna_tf32u(float x) {
    u32 r;
    asm("cvt.rna.tf32.f32 %0, %1;" : "=r"(r) : "f"(x));
    return r;
}
__device__ __forceinline__ void cpa16(float* dst, const void* g) {
    u32 a = (u32)__cvta_generic_to_shared(dst);
    asm volatile("cp.async.cg.shared.global [%0], [%1], 16;" :: "r"(a), "l"(g));
}
__device__ __forceinline__ void cpa_commit() { asm volatile("cp.async.commit_group;"); }
__device__ __forceinline__ void cpa_wait0() { asm volatile("cp.async.wait_group 0;" ::: "memory"); }

// D += A(16x8,row) * B(8x8,col), tf32
__device__ __forceinline__ void mma8(float* c, const u32* a, u32 b0, u32 b1) {
    asm volatile(
        "mma.sync.aligned.m16n8k8.row.col.f32.tf32.tf32.f32 "
        "{%0,%1,%2,%3}, {%4,%5,%6,%7}, {%8,%9}, {%0,%1,%2,%3};"
        : "+f"(c[0]), "+f"(c[1]), "+f"(c[2]), "+f"(c[3])
        : "r"(a[0]), "r"(a[1]), "r"(a[2]), "r"(a[3]), "r"(b0), "r"(b1));
}
__device__ __forceinline__ u32 ldsf(const float* p) { return __float_as_uint(*p); }

// ---------------- main fused kernel ----------------
__global__ __launch_bounds__(THREADS, 1)
void td_kernel(const float* __restrict__ z, const float* __restrict__ cc,
               const float* __restrict__ tdm, const float* __restrict__ Wz,
               const float* __restrict__ Wa, const float* __restrict__ Wu,
               const float* __restrict__ zg, const float* __restrict__ zb,
               const float* __restrict__ vg, const float* __restrict__ vb,
               float* __restrict__ out)
{
    extern __shared__ float smf[];
    const int t = threadIdx.x;
    const int wid = t >> 5, lane = t & 31;
    const int g = lane >> 2, tg = lane & 3;

    // ---- prefetch first tile (overlaps weight staging) ----
    const int tile0 = blockIdx.x;
    {
        const float* src = z + (size_t)tile0 * TM * TZ;
        #pragma unroll
        for (int i = 0; i < 16; i++) {
            int e = i * THREADS + t;            // 0..4095 float4
            cpa16(&smf[ZA0_F + (e >> 5) * ZSTR + (e & 31) * 4], src + e * 4);
        }
        cpa_commit();
    }

    // ---- one-time weight staging ----
    for (int s = t; s < TZ * TD; s += THREADS) {        // W1'[k][n] = Wz[n][k]*zg[k]
        int k = s >> 6, n = s & 63;
        smf[W1_F + k * W1STR + n] = rna_tf32(Wz[n * TZ + k] * zg[k]);
    }
    for (int s = t; s < TD * TZ; s += THREADS) {        // W2[d][c] = Wu[c][d]
        int d = s >> 7, c = s & 127;
        smf[W2_F + d * W2STR + c] = rna_tf32(Wu[c * TD + d]);
    }
    for (int s = t; s < NB * TD; s += THREADS) {        // Was[bin][d]
        int k = s >> 6, d = s & 63;
        smf[WAS_F + k * TD + d] = Wa[d * NB + k];
    }
    if (t < TD) {
        float S = 0.f, T = 0.f;
        for (int k = 0; k < TZ; k++) {
            S += rna_tf32(Wz[t * TZ + k] * zg[k]);
            T += Wz[t * TZ + k] * zb[k];
        }
        smf[S_F + t] = S; smf[T_F + t] = T;
        smf[VG_F + t] = vg[t]; smf[VB_F + t] = vb[t];
    }

    const int rb = wid >> 1, ch = wid & 1;     // warp grid 4x2
    const int R1 = rb * 32, C1 = ch * 32;      // GEMM1 tile base
    const int C2 = ch * 64;                    // GEMM2 col base

    int cur = 0;
    for (int tile = tile0; tile < NTILES; tile += NBLOCKS) {
        const int base_p = tile * TM;
        const int nt_idx = tile + NBLOCKS;
        float* zc = &smf[cur ? ZA1_F : ZA0_F];
        float* zn = &smf[cur ? ZA0_F : ZA1_F];

        cpa_wait0();
        __syncthreads();   // zc ready; all warps past last tile's GEMM2 (zn free)

        // prefetch next tile (fully overlapped with GEMM1/epilogues)
        if (nt_idx < NTILES) {
            const float* src = z + (size_t)nt_idx * TM * TZ;
            #pragma unroll
            for (int i = 0; i < 16; i++) {
                int e = i * THREADS + t;
                cpa16(&zn[(e >> 5) * ZSTR + (e & 31) * 4], src + e * 4);
            }
            cpa_commit();
        }

        // ---- per-thread distance bin + mask for this thread's 4 output rows ----
        int binreg[4];
        float mkreg[4];
        {
            const int i0 = base_p >> 10;
            const int jb = base_p & (N_TOK - 1);
            const float cx = __ldg(cc + i0 * 3 + 0);
            const float cy = __ldg(cc + i0 * 3 + 1);
            const float cz = __ldg(cc + i0 * 3 + 2);
            #pragma unroll
            for (int i = 0; i < 4; i++) {
                const int row = R1 + g + 8 * i;
                const int j0 = jb + row;
                float dx = cx - __ldg(cc + j0 * 3 + 0);
                float dy = cy - __ldg(cc + j0 * 3 + 1);
                float dz = cz - __ldg(cc + j0 * 3 + 2);
                float dist = sqrtf(dx * dx + dy * dy + dz * dz);
                int idx = 0;
                #pragma unroll
                for (int k = 0; k < NB - 1; k++) {
                    float b = (float)(3.25 + k * (47.5 / 36.0));
                    idx += (dist > b) ? 1 : 0;
                }
                binreg[i] = idx;
                mkreg[i] = __ldg(tdm + base_p + row);
            }
        }

        // ---- GEMM1 + fused LN1 stats: v = z @ W1'^T, warp tile 32x32 ----
        float acc[2][4][4];
        #pragma unroll
        for (int a = 0; a < 2; a++)
            #pragma unroll
            for (int b = 0; b < 4; b++)
                #pragma unroll
                for (int cI = 0; cI < 4; cI++) acc[a][b][cI] = 0.f;

        float sst[4] = {0.f, 0.f, 0.f, 0.f};   // raw row sums (slots: rows R1+g+8i)
        float sqt[4] = {0.f, 0.f, 0.f, 0.f};   // raw row sumsq

        #pragma unroll 4
        for (int ks = 0; ks < 16; ks++) {
            const int k0 = ks * 8;
            u32 afr[2][4];
            #pragma unroll
            for (int rt = 0; rt < 2; rt++) {
                const float* zr = &zc[(R1 + 16 * rt + g) * ZSTR + k0 + tg];
                float v0 = zr[0];              // row R1+16rt+g,   k0+tg
                float v1 = zr[8 * ZSTR];       // row R1+16rt+8+g, k0+tg
                float v2 = zr[4];              // row R1+16rt+g,   k0+tg+4
                float v3 = zr[8 * ZSTR + 4];   // row R1+16rt+8+g, k0+tg+4
                sst[2 * rt + 0] += v0 + v2;
                sqt[2 * rt + 0] += v0 * v0 + v2 * v2;
                sst[2 * rt + 1] += v1 + v3;
                sqt[2 * rt + 1] += v1 * v1 + v3 * v3;
                afr[rt][0] = rna_tf32u(v0);
                afr[rt][1] = rna_tf32u(v1);
                afr[rt][2] = rna_tf32u(v2);
                afr[rt][3] = rna_tf32u(v3);
            }
            #pragma unroll
            for (int nt = 0; nt < 4; nt++) {
                const float* wr = &smf[W1_F + (k0 + tg) * W1STR + C1 + 8 * nt + g];
                u32 b0 = ldsf(wr);
                u32 b1 = ldsf(wr + 4 * W1STR);
                mma8(acc[0][nt], afr[0], b0, b1);
                mma8(acc[1][nt], afr[1], b0, b1);
            }
        }

        // finalize LN1 stats per row-slot (reduce over the 4 tg lanes)
        float m1r[4], rs1r[4];
        #pragma unroll
        for (int i = 0; i < 4; i++) {
            float s = sst[i], q = sqt[i];
            s += __shfl_xor_sync(0xffffffffu, s, 1);
            q += __shfl_xor_sync(0xffffffffu, q, 1);
            s += __shfl_xor_sync(0xffffffffu, s, 2);
            q += __shfl_xor_sync(0xffffffffu, q, 2);
            float m = s * (1.f / TZ);
            float var = fmaxf(q * (1.f / TZ) - m * m, 0.f);
            m1r[i] = m;
            rs1r[i] = rsqrtf(var + EPSF);
        }

        // ---- epilogue 1: LN1-fold + bin column + LN2 partials ----
        #pragma unroll
        for (int i = 0; i < 4; i++) {
            const int row = R1 + g + 8 * i;
            const int rt = i >> 1, cp = (i & 1) * 2;
            const float m1 = m1r[i], r1 = rs1r[i], mk = mkreg[i];
            const int bin = binreg[i];
            float s2 = 0.f, q2 = 0.f;
            #pragma unroll
            for (int nt = 0; nt < 4; nt++) {
                const int col = C1 + 8 * nt + 2 * tg;
                float2 Sv = *(const float2*)&smf[S_F + col];
                float2 Tv = *(const float2*)&smf[T_F + col];
                float2 Wv = *(const float2*)&smf[WAS_F + bin * TD + col];
                float v0 = r1 * (acc[rt][nt][cp]     - m1 * Sv.x) + Tv.x + mk * Wv.x;
                float v1 = r1 * (acc[rt][nt][cp + 1] - m1 * Sv.y) + Tv.y + mk * Wv.y;
                acc[rt][nt][cp] = v0; acc[rt][nt][cp + 1] = v1;
                s2 += v0 + v1;
                q2 += v0 * v0 + v1 * v1;
            }
            s2 += __shfl_xor_sync(0xffffffffu, s2, 1);
            q2 += __shfl_xor_sync(0xffffffffu, q2, 1);
            s2 += __shfl_xor_sync(0xffffffffu, s2, 2);
            q2 += __shfl_xor_sync(0xffffffffu, q2, 2);
            if (tg == 0)
                *(float2*)&smf[LN2_F + row * 4 + ch * 2] = make_float2(s2, q2);
        }
        __syncthreads();

        // ---- LN2 finalize + relu + tf32 -> vn (aliases zc) ----
        float* vn = zc;
        #pragma unroll
        for (int i = 0; i < 4; i++) {
            const int row = R1 + g + 8 * i;
            const int rt = i >> 1, cp = (i & 1) * 2;
            float4 o = *(const float4*)&smf[LN2_F + row * 4];
            float st = o.x + o.z, qt = o.y + o.w;
            float m2 = st * (1.f / TD);
            float var = fmaxf(qt * (1.f / TD) - m2 * m2, 0.f);
            float sc = 2.f * rsqrtf(4.f * var + EPSF);    // exact v+v doubling
            #pragma unroll
            for (int nt = 0; nt < 4; nt++) {
                const int col = C1 + 8 * nt + 2 * tg;
                float2 gv = *(const float2*)&smf[VG_F + col];
                float2 bv = *(const float2*)&smf[VB_F + col];
                float2 r;
                r.x = rna_tf32(fmaxf(fmaf((acc[rt][nt][cp]     - m2) * sc, gv.x, bv.x), 0.f));
                r.y = rna_tf32(fmaxf(fmaf((acc[rt][nt][cp + 1] - m2) * sc, gv.y, bv.y), 0.f));
                *(float2*)&vn[row * VSTR + col] = r;
            }
        }
        __syncthreads();

        // ---- GEMM2: u[128x128] = vn @ W2^T, warp tile 32x64 + direct STG ----
        float acc2[2][8][4];
        #pragma unroll
        for (int a = 0; a < 2; a++)
            #pragma unroll
            for (int b = 0; b < 8; b++)
                #pragma unroll
                for (int cI = 0; cI < 4; cI++) acc2[a][b][cI] = 0.f;

        #pragma unroll 2
        for (int ks = 0; ks < 8; ks++) {
            const int k0 = ks * 8;
            u32 afr[2][4];
            #pragma unroll
            for (int rt = 0; rt < 2; rt++) {
                const float* vr = &vn[(R1 + 16 * rt + g) * VSTR + k0 + tg];
                afr[rt][0] = ldsf(vr);
                afr[rt][2] = ldsf(vr + 4);
                afr[rt][1] = ldsf(vr + 8 * VSTR);
                afr[rt][3] = ldsf(vr + 8 * VSTR + 4);
            }
            #pragma unroll
            for (int nt = 0; nt < 8; nt++) {
                const float* wr = &smf[W2_F + (k0 + tg) * W2STR + C2 + 8 * nt + g];
                u32 b0 = ldsf(wr);
                u32 b1 = ldsf(wr + 4 * W2STR);
                mma8(acc2[0][nt], afr[0], b0, b1);
                mma8(acc2[1][nt], afr[1], b0, b1);
            }
        }
        // epilogue 2: STG.64 per C-pair
        #pragma unroll
        for (int rt = 0; rt < 2; rt++) {
            const int ra = base_p + R1 + 16 * rt + g;
            #pragma unroll
            for (int nt = 0; nt < 8; nt++) {
                const int col = C2 + 8 * nt + 2 * tg;
                *(float2*)&out[(size_t)ra * TZ + col] =
                    make_float2(acc2[rt][nt][0], acc2[rt][nt][1]);
                *(float2*)&out[(size_t)(ra + 8) * TZ + col] =
                    make_float2(acc2[rt][nt][2], acc2[rt][nt][3]);
            }
        }
        cur ^= 1;
    }
}

// ---------------- launch ----------------
extern "C" void kernel_launch(void* const* d_in, const int* in_sizes, int n_in,
                              void* d_out, int out_size) {
    const float* z   = (const float*)d_in[0];   // (1,1024,1024,128)
    const float* cc  = (const float*)d_in[1];   // (1,1024,3)
    const float* tdm = (const float*)d_in[2];   // (1,1024,1024)
    // d_in[3] = pair_mask (unused by reference)
    const float* Wz  = (const float*)d_in[4];   // (64,128)
    const float* Wa  = (const float*)d_in[5];   // (64,38)
    const float* Wu  = (const float*)d_in[6];   // (128,64)
    const float* zg  = (const float*)d_in[7];   // (128)
    const float* zb  = (const float*)d_in[8];   // (128)
    const float* vg  = (const float*)d_in[9];   // (64)
    const float* vb  = (const float*)d_in[10];  // (64)
    float* out = (float*)d_out;

    size_t smem_bytes = (size_t)SMEM_FLOATS * sizeof(float);
    cudaFuncSetAttribute(td_kernel, cudaFuncAttributeMaxDynamicSharedMemorySize, (int)smem_bytes);
    td_kernel<<<NBLOCKS, THREADS, smem_bytes>>>(z, cc, tdm, Wz, Wa, Wu, zg, zb, vg, vb, out);
}